// round 16
// baseline (speedup 1.0000x reference)
#include <cuda_runtime.h>
#include <cuda_bf16.h>
#include <cuda_fp16.h>
#include <cuda_pipeline.h>
#include <mma.h>
#include <math.h>

#define B_  512
#define S_  200
#define D_  512
#define NH_ 8
#define L_  4
#define CH  32

// ---------------- scratch (device globals) ----------------------------------
__device__ float g_hblk[B_*L_*D_];
__device__ float g_valid[B_*L_];
__device__ float g_a[B_*L_];
__device__ float g_s1[B_*L_];
__device__ float g_bt[B_*D_];
__device__ __half g_Hh[B_*S_*D_];        // 105 MB (fp16 H)
__device__ float g_uK[B_*NH_*D_];
__device__ float g_ctx[2*B_*NH_*D_];     // 2 chunk-split partials
__device__ float g_psum[2*B_*NH_];
__device__ float g_mt[B_*D_];
__device__ float g_zero512[512];         // statically zero
__device__ float g_partC[2*B_*2048];     // comb / W1 split-K partials
__device__ float g_partM[4*B_*D_];       // mraw split-K partials
__device__ float g_partG[2*B_*1536];     // gi split-K partials

// bf16 hi/lo split weights, [N][K] layout (K contiguous)
__device__ __nv_bfloat16 g_combT_h[2048*512];
__device__ __nv_bfloat16 g_combT_l[2048*512];
__device__ __nv_bfloat16 g_Wih_h[1536*512];
__device__ __nv_bfloat16 g_Wih_l[1536*512];
__device__ __nv_bfloat16 g_Wk_h[512*512];
__device__ __nv_bfloat16 g_Wk_l[512*512];
__device__ __nv_bfloat16 g_WvT_h[512*512];
__device__ __nv_bfloat16 g_WvT_l[512*512];
__device__ __nv_bfloat16 g_W1T_h[512*512];
__device__ __nv_bfloat16 g_W1T_l[512*512];

#define PC1_OFF 1048576L   // 512*2048
#define PM_OFF  262144L    // 512*512
#define PG1_OFF 786432L    // 512*1536
#define CTX_OFF 2097152L   // 512*8*512
#define PS1_OFF 4096L      // 512*8

// dynamic smem: 2 stages x (A(64) h/l + B(BN) h/l) x RS(40) x 2B
#define SMEM_TCB128 61440
#define SMEM_TCB64  40960

// attention v5 smem layout (bytes)
#define AHS_ROW   520                       // halfs per Hs row (512 + 8 pad)
#define APT_ROW   40                        // halfs per psT row (32 + 8 pad)
#define AOFF_HS   0                         // 32 x 520 half = 33280
#define AOFF_UKH  33280                     // 8 x 520 half = 8320
#define AOFF_UKL  41600                     // 8 x 520 half = 8320
#define AOFF_SC   49920                     // 8 x 256 float = 8192
#define AOFF_PS   58112                     // 32 x 8 float = 1024
#define AOFF_PTH  59136                     // 8 x 40 half = 640
#define AOFF_PTL  59776                     // 8 x 40 half = 640
#define AOFF_CK   60416                     // 8 float
#define AOFF_PSS  60448                     // 8 float
#define ATTN_SMEM_V5 60480

// PDL helpers
__device__ __forceinline__ void pdl_sync() {
#if __CUDA_ARCH__ >= 900
    cudaGridDependencySynchronize();
    cudaTriggerProgrammaticLaunchCompletion();
#endif
}

// ---------------- helpers ----------------------------------------------------
__device__ __forceinline__ float warpSum(float v) {
    #pragma unroll
    for (int o = 16; o; o >>= 1) v += __shfl_down_sync(0xffffffffu, v, o);
    return v;
}
__device__ __forceinline__ float warpAll(float v) {
    #pragma unroll
    for (int o = 16; o; o >>= 1) v += __shfl_xor_sync(0xffffffffu, v, o);
    return v;
}
__device__ __forceinline__ float warpMax(float v) {
    #pragma unroll
    for (int o = 16; o; o >>= 1) v = fmaxf(v, __shfl_down_sync(0xffffffffu, v, o));
    return v;
}
__device__ __forceinline__ float blockSum(float v, float* red) {
    int lane = threadIdx.x & 31, w = threadIdx.x >> 5;
    v = warpSum(v);
    if (lane == 0) red[w] = v;
    __syncthreads();
    float r = 0.f;
    if (threadIdx.x < (blockDim.x >> 5)) r = red[threadIdx.x];
    if (w == 0) r = warpSum(r);
    if (threadIdx.x == 0) red[0] = r;
    __syncthreads();
    r = red[0];
    __syncthreads();
    return r;
}
__device__ __forceinline__ float blockMax(float v, float* red) {
    int lane = threadIdx.x & 31, w = threadIdx.x >> 5;
    v = warpMax(v);
    if (lane == 0) red[w] = v;
    __syncthreads();
    float r = -3.0e38f;
    if (threadIdx.x < (blockDim.x >> 5)) r = red[threadIdx.x];
    if (w == 0) r = warpMax(r);
    if (threadIdx.x == 0) red[0] = r;
    __syncthreads();
    r = red[0];
    __syncthreads();
    return r;
}
__device__ __forceinline__ float sigm(float x) { return 1.f / (1.f + expf(-x)); }

// ---------------- WMMA tensor GEMM core v2 (unchanged from R15) ----------------
template <int BN, bool COMPOSE>
__device__ __forceinline__ void tc_core(
    const float* A0, const float* A1, const float* Ab, int lda,
    const __nv_bfloat16* Bh, const __nv_bfloat16* Bl, int ldb,
    float* C, int ldc, int Kd, int m0, int n0)
{
    const int RS = 40;
    const int NT = BN / 64;
    const int BCH = BN / 64;
    const int AE = 64 * RS;
    const int BE = BN * RS;
    const int STG = 2 * AE + 2 * BE;

    extern __shared__ __align__(16) __nv_bfloat16 dsm[];

    pdl_sync();

    int tid = threadIdx.x;
    int warp = tid >> 5;
    int wm = warp & 1;
    int wn = warp >> 1;

    nvcuda::wmma::fragment<nvcuda::wmma::accumulator, 16, 16, 16, float> acc[2][NT];
    #pragma unroll
    for (int i = 0; i < 2; i++) {
        #pragma unroll
        for (int j = 0; j < NT; j++) {
            nvcuda::wmma::fill_fragment(acc[i][j], 0.0f);
        }
    }

    float4 va[2];
    int arow = tid >> 3;
    int aq = tid & 7;

    {
        __nv_bfloat16* sBh = dsm + 2 * AE;
        __nv_bfloat16* sBl = dsm + 2 * AE + BE;
        #pragma unroll
        for (int i = 0; i < BCH; i++) {
            int c = tid + i * 256;
            int row = c >> 2;
            int q = c & 3;
            __pipeline_memcpy_async(sBh + row * RS + q * 8,
                                    Bh + (long)(n0 + row) * ldb + q * 8, 16);
            __pipeline_memcpy_async(sBl + row * RS + q * 8,
                                    Bl + (long)(n0 + row) * ldb + q * 8, 16);
        }
        __pipeline_commit();
        #pragma unroll
        for (int i = 0; i < 2; i++) {
            int row = arow + i * 32;
            float4 v = *(const float4*)(A0 + (long)(m0 + row) * lda + aq * 4);
            if (COMPOSE) {
                float4 v1 = *(const float4*)(A1 + (long)(m0 + row) * lda + aq * 4);
                float4 bi = *(const float4*)(Ab + aq * 4);
                v.x += v1.x + bi.x; v.y += v1.y + bi.y;
                v.z += v1.z + bi.z; v.w += v1.w + bi.w;
            }
            va[i] = v;
        }
        __nv_bfloat16* sAh = dsm;
        __nv_bfloat16* sAl = dsm + AE;
        #pragma unroll
        for (int i = 0; i < 2; i++) {
            int row = arow + i * 32;
            float4 v = va[i];
            __nv_bfloat16 h0 = __float2bfloat16(v.x);
            __nv_bfloat16 h1 = __float2bfloat16(v.y);
            __nv_bfloat16 h2 = __float2bfloat16(v.z);
            __nv_bfloat16 h3 = __float2bfloat16(v.w);
            int o = row * RS + aq * 4;
            sAh[o + 0] = h0; sAh[o + 1] = h1; sAh[o + 2] = h2; sAh[o + 3] = h3;
            sAl[o + 0] = __float2bfloat16(v.x - __bfloat162float(h0));
            sAl[o + 1] = __float2bfloat16(v.y - __bfloat162float(h1));
            sAl[o + 2] = __float2bfloat16(v.z - __bfloat162float(h2));
            sAl[o + 3] = __float2bfloat16(v.w - __bfloat162float(h3));
        }
        __pipeline_wait_prior(0);
        __syncthreads();
    }

    int nch = Kd >> 5;
    for (int c = 0; c < nch; c++) {
        int kn = (c + 1) * 32;
        __nv_bfloat16* nxt = dsm + ((c + 1) & 1) * STG;
        if (c + 1 < nch) {
            __nv_bfloat16* sBh = nxt + 2 * AE;
            __nv_bfloat16* sBl = nxt + 2 * AE + BE;
            #pragma unroll
            for (int i = 0; i < BCH; i++) {
                int cc = tid + i * 256;
                int row = cc >> 2;
                int q = cc & 3;
                __pipeline_memcpy_async(sBh + row * RS + q * 8,
                                        Bh + (long)(n0 + row) * ldb + kn + q * 8, 16);
                __pipeline_memcpy_async(sBl + row * RS + q * 8,
                                        Bl + (long)(n0 + row) * ldb + kn + q * 8, 16);
            }
            __pipeline_commit();
            #pragma unroll
            for (int i = 0; i < 2; i++) {
                int row = arow + i * 32;
                float4 v = *(const float4*)(A0 + (long)(m0 + row) * lda + kn + aq * 4);
                if (COMPOSE) {
                    float4 v1 = *(const float4*)(A1 + (long)(m0 + row) * lda + kn + aq * 4);
                    float4 bi = *(const float4*)(Ab + kn + aq * 4);
                    v.x += v1.x + bi.x; v.y += v1.y + bi.y;
                    v.z += v1.z + bi.z; v.w += v1.w + bi.w;
                }
                va[i] = v;
            }
        }
        {
            __nv_bfloat16* base = dsm + (c & 1) * STG;
            __nv_bfloat16* sAh = base;
            __nv_bfloat16* sAl = base + AE;
            __nv_bfloat16* sBh = base + 2 * AE;
            __nv_bfloat16* sBl = base + 2 * AE + BE;
            #pragma unroll
            for (int ks = 0; ks < 2; ks++) {
                nvcuda::wmma::fragment<nvcuda::wmma::matrix_a, 16, 16, 16,
                                       __nv_bfloat16, nvcuda::wmma::row_major> ah[2], al[2];
                #pragma unroll
                for (int i = 0; i < 2; i++) {
                    int r = wm * 32 + i * 16;
                    nvcuda::wmma::load_matrix_sync(ah[i], sAh + r * RS + ks * 16, RS);
                    nvcuda::wmma::load_matrix_sync(al[i], sAl + r * RS + ks * 16, RS);
                }
                #pragma unroll
                for (int j = 0; j < NT; j++) {
                    int nn = wn * (BN / 4) + j * 16;
                    nvcuda::wmma::fragment<nvcuda::wmma::matrix_b, 16, 16, 16,
                                           __nv_bfloat16, nvcuda::wmma::col_major> bh, bl;
                    nvcuda::wmma::load_matrix_sync(bh, sBh + nn * RS + ks * 16, RS);
                    nvcuda::wmma::load_matrix_sync(bl, sBl + nn * RS + ks * 16, RS);
                    #pragma unroll
                    for (int i = 0; i < 2; i++) {
                        nvcuda::wmma::mma_sync(acc[i][j], ah[i], bh, acc[i][j]);
                        nvcuda::wmma::mma_sync(acc[i][j], ah[i], bl, acc[i][j]);
                        nvcuda::wmma::mma_sync(acc[i][j], al[i], bh, acc[i][j]);
                    }
                }
            }
        }
        if (c + 1 < nch) {
            __nv_bfloat16* sAh = nxt;
            __nv_bfloat16* sAl = nxt + AE;
            #pragma unroll
            for (int i = 0; i < 2; i++) {
                int row = arow + i * 32;
                float4 v = va[i];
                __nv_bfloat16 h0 = __float2bfloat16(v.x);
                __nv_bfloat16 h1 = __float2bfloat16(v.y);
                __nv_bfloat16 h2 = __float2bfloat16(v.z);
                __nv_bfloat16 h3 = __float2bfloat16(v.w);
                int o = row * RS + aq * 4;
                sAh[o + 0] = h0; sAh[o + 1] = h1; sAh[o + 2] = h2; sAh[o + 3] = h3;
                sAl[o + 0] = __float2bfloat16(v.x - __bfloat162float(h0));
                sAl[o + 1] = __float2bfloat16(v.y - __bfloat162float(h1));
                sAl[o + 2] = __float2bfloat16(v.z - __bfloat162float(h2));
                sAl[o + 3] = __float2bfloat16(v.w - __bfloat162float(h3));
            }
            __pipeline_wait_prior(0);
        }
        __syncthreads();
    }
    #pragma unroll
    for (int i = 0; i < 2; i++) {
        #pragma unroll
        for (int j = 0; j < NT; j++) {
            int row = m0 + wm * 32 + i * 16;
            int col = n0 + wn * (BN / 4) + j * 16;
            nvcuda::wmma::store_matrix_sync(C + (long)row * ldc + col, acc[i][j],
                                            ldc, nvcuda::wmma::mem_row_major);
        }
    }
}

// ---------------- GEMM wrapper kernels (BM=64, 2 CTAs/SM) ----------------------
__global__ __launch_bounds__(256, 2) void k_tc_w1()
{
    int z = blockIdx.z;
    tc_core<128, false>(g_hblk + z * 256, (const float*)0, (const float*)0, 512,
                        g_W1T_h + z * 256, g_W1T_l + z * 256, 512,
                        g_partC + (long)z * PC1_OFF, 512, 256,
                        blockIdx.y * 64, blockIdx.x * 128);
}
__global__ __launch_bounds__(256, 2) void k_tc_q()
{
    int z = blockIdx.z;
    tc_core<128, false>(g_bt + z * 256, (const float*)0, (const float*)0, 512,
                        g_combT_h + z * 256, g_combT_l + z * 256, 512,
                        g_partC + (long)z * PC1_OFF, 2048, 256,
                        blockIdx.y * 64, blockIdx.x * 128);
}
__global__ __launch_bounds__(256, 2) void k_tc_gh()
{
    int z = blockIdx.z;
    tc_core<128, false>(g_bt + z * 256, (const float*)0, (const float*)0, 512,
                        g_combT_h + (long)512 * 512 + z * 256,
                        g_combT_l + (long)512 * 512 + z * 256, 512,
                        g_partC + (long)z * PC1_OFF + 512, 2048, 256,
                        blockIdx.y * 64, blockIdx.x * 128);
}
__global__ __launch_bounds__(256, 2) void k_tc_uk(const float* __restrict__ bq)
{
    int h = blockIdx.z;
    tc_core<128, true>(g_partC + h * 64, g_partC + PC1_OFF + h * 64, bq + h * 64, 2048,
                       g_Wk_h + h * 64, g_Wk_l + h * 64, 512,
                       g_uK + h * 512, 4096, 64,
                       blockIdx.y * 64, blockIdx.x * 128);
}
// mraw: A = ctx part0 + ctx part1 (COMPOSE with zero bias); z = h*4 + ksplit
__global__ __launch_bounds__(256, 2) void k_tc_mraw()
{
    int z = blockIdx.z;
    int h = z >> 2;
    int ks = z & 3;
    tc_core<64, true>(g_ctx + h * 512 + (long)ks * 128,
                      g_ctx + CTX_OFF + h * 512 + (long)ks * 128,
                      g_zero512, 4096,
                      g_WvT_h + (long)(h * 64) * 512 + ks * 128,
                      g_WvT_l + (long)(h * 64) * 512 + ks * 128, 512,
                      g_partM + ks * PM_OFF + h * 64, 512, 128,
                      blockIdx.y * 64, 0);
}
__global__ __launch_bounds__(256, 2) void k_tc_gi()
{
    int z = blockIdx.z;
    tc_core<128, false>(g_mt + z * 256, (const float*)0, (const float*)0, 512,
                        g_Wih_h + z * 256, g_Wih_l + z * 256, 512,
                        g_partG + (long)z * PG1_OFF, 1536, 256,
                        blockIdx.y * 64, blockIdx.x * 128);
}

// ---------------- weight prep (jbase selects job subset) -----------------------
__global__ __launch_bounds__(256) void k_prep(
    const float* __restrict__ Wk, const float* __restrict__ W_ih,
    const float* __restrict__ W_hh, const float* __restrict__ Wq,
    const float* __restrict__ Wv, const float* __restrict__ W1, int jbase)
{
    __shared__ float t[32][33];
    int job = blockIdx.z + jbase;
    int bx = blockIdx.x * 32;
    int by = blockIdx.y * 32;
    int lx = threadIdx.x & 31;
    int wy = threadIdx.x >> 5;
    if (job <= 2) {
        const float* src;
        __nv_bfloat16* dh;
        __nv_bfloat16* dl;
        int nrows;
        if (job == 0)      { src = Wk;   dh = g_Wk_h;  dl = g_Wk_l;  nrows = 512;  }
        else if (job == 1) { src = W_ih; dh = g_Wih_h; dl = g_Wih_l; nrows = 1536; }
        else               { src = W_hh; dh = g_combT_h + 512*512;
                             dl = g_combT_l + 512*512; nrows = 1536; }
        if (by >= nrows) return;
        for (int j = wy; j < 32; j += 8) {
            long o = (long)(by + j) * 512 + bx + lx;
            float v = src[o];
            __nv_bfloat16 hh = __float2bfloat16(v);
            dh[o] = hh;
            dl[o] = __float2bfloat16(v - __bfloat162float(hh));
        }
    } else {
        if (blockIdx.y >= 16) return;
        const float* src;
        __nv_bfloat16* dh;
        __nv_bfloat16* dl;
        if (job == 3)      { src = Wq; dh = g_combT_h; dl = g_combT_l; }
        else if (job == 4) { src = Wv; dh = g_WvT_h;   dl = g_WvT_l;   }
        else               { src = W1; dh = g_W1T_h;   dl = g_W1T_l;   }
        for (int j = wy; j < 32; j += 8)
            t[j][lx] = src[(long)(by + j) * 512 + bx + lx];
        __syncthreads();
        for (int j = wy; j < 32; j += 8) {
            float v = t[lx][j];
            long o = (long)(bx + j) * 512 + by + lx;
            __nv_bfloat16 hh = __float2bfloat16(v);
            dh[o] = hh;
            dl[o] = __float2bfloat16(v - __bfloat162float(hh));
        }
    }
}

// ---------------- preamble -----------------------------------------------------
__global__ __launch_bounds__(512) void k_build_hblk(
    const float* __restrict__ emb, const int* __restrict__ stc,
    const int* __restrict__ off, const int* __restrict__ sep)
{
    pdl_sync();
    int b = blockIdx.x;
    int o = off[b], len = stc[b];
    int sA = sep[b * 2], sB2 = sep[b * 2 + 1];
    int idx = (sA < o ? 1 : 0) + (sB2 < o ? 1 : 0);
    int pidx = idx - 1; pidx = pidx < 0 ? 0 : (pidx > 1 ? 1 : pidx);
    int prev = (pidx == 0) ? sA : sB2;
    int left = (idx > 0) ? prev + 1 : 0;
    int nidx = idx > 1 ? 1 : idx;
    int nxt = (nidx == 0) ? sA : sB2;
    int right = (idx < 2) ? nxt : len;
    int start = (o - 2 > left) ? o - 2 : left;
    int end = (o + 2 < right) ? o + 2 : right;
    int t = threadIdx.x;
    #pragma unroll
    for (int l = 0; l < L_; l++) {
        int ind = start + l;
        bool v = ind < end;
        int ic = ind < 0 ? 0 : (ind > S_ - 1 ? S_ - 1 : ind);
        g_hblk[(b * L_ + l) * D_ + t] = v ? emb[((long)b * S_ + ic) * D_ + t] : 0.f;
        if (t == 0) g_valid[b * L_ + l] = v ? 1.f : 0.f;
    }
}

__global__ __launch_bounds__(256) void k_a(const float* __restrict__ W2)
{
    pdl_sync();
    int m = blockIdx.x, t = threadIdx.x;
    float t0 = tanhf(g_partC[(long)m * 512 + t] + g_partC[PC1_OFF + (long)m * 512 + t]);
    float t1 = tanhf(g_partC[(long)m * 512 + t + 256] + g_partC[PC1_OFF + (long)m * 512 + t + 256]);
    float v = t0 * W2[t] + t1 * W2[t + 256];
    __shared__ float red[32];
    v = blockSum(v, red);
    if (t == 0) g_a[m] = v;
}

__global__ __launch_bounds__(512) void k_s1()
{
    pdl_sync();
    int l = blockIdx.x, t = threadIdx.x;
    __shared__ float red[32];
    float v = g_a[t * L_ + l];
    float mx = blockMax(v, red);
    float e = expf(v - mx);
    float s = blockSum(e, red);
    g_s1[t * L_ + l] = e / s;
}

__global__ __launch_bounds__(512) void k_b0(
    const float* __restrict__ ln_g, const float* __restrict__ ln_b,
    const float* __restrict__ pe)
{
    pdl_sync();
    int b = blockIdx.x, t = threadIdx.x;
    __shared__ float sc[4];
    __shared__ float red[32];
    if (t == 0) {
        float vals[4], mx = -3.0e38f;
        #pragma unroll
        for (int l = 0; l < 4; l++) {
            float v = (g_valid[b * 4 + l] > 0.5f) ? g_s1[b * 4 + l] : -1e9f;
            vals[l] = v; mx = fmaxf(mx, v);
        }
        float s = 0.f;
        #pragma unroll
        for (int l = 0; l < 4; l++) { float e = expf(vals[l] - mx); sc[l] = e; s += e; }
        #pragma unroll
        for (int l = 0; l < 4; l++) sc[l] /= s;
    }
    __syncthreads();
    float x = sc[0] * g_hblk[(b * 4 + 0) * D_ + t] + sc[1] * g_hblk[(b * 4 + 1) * D_ + t]
            + sc[2] * g_hblk[(b * 4 + 2) * D_ + t] + sc[3] * g_hblk[(b * 4 + 3) * D_ + t]
            + pe[t];
    float mean = blockSum(x, red) * (1.f / 512.f);
    float d = x - mean;
    float var = blockSum(d * d, red) * (1.f / 512.f);
    g_bt[b * D_ + t] = d * rsqrtf(var + 1e-5f) * ln_g[t] + ln_b[t];
}

// warp-per-row H build
__global__ __launch_bounds__(256) void k_buildH(
    const float* __restrict__ emb, const float* __restrict__ pe,
    const float* __restrict__ seg_emb, const float* __restrict__ ln_g,
    const float* __restrict__ ln_b, const int* __restrict__ stc,
    const int* __restrict__ off)
{
    __shared__ float s_seg[2][D_];
    __shared__ float s_g[D_];
    __shared__ float s_b[D_];
    int b = blockIdx.x;
    int tid = threadIdx.x, lane = tid & 31, warp = tid >> 5;
    for (int i = tid; i < D_; i += 256) {
        s_seg[0][i] = seg_emb[i];
        s_seg[1][i] = seg_emb[D_ + i];
        s_g[i] = ln_g[i];
        s_b[i] = ln_b[i];
    }
    int len = stc[b];
    int pos = off[b];
    __syncthreads();
    for (int s = warp; s < len; s += 8) {
        int ip = (s < pos) ? (pos - s) : (s + 1 - pos);
        ip = ip < 0 ? 0 : (ip > S_ ? S_ : ip);
        int sg = (s >= pos) ? 1 : 0;
        const float* er = emb + ((long)b * S_ + s) * D_;
        const float* pr = pe + (long)ip * D_;
        float x[16];
        float sum = 0.f;
        #pragma unroll
        for (int i = 0; i < 4; i++) {
            int base = i * 128 + lane * 4;
            float4 e = *(const float4*)(er + base);
            float4 p = *(const float4*)(pr + base);
            float v0 = e.x + p.x + s_seg[sg][base + 0];
            float v1 = e.y + p.y + s_seg[sg][base + 1];
            float v2 = e.z + p.z + s_seg[sg][base + 2];
            float v3 = e.w + p.w + s_seg[sg][base + 3];
            x[i*4+0] = v0; x[i*4+1] = v1; x[i*4+2] = v2; x[i*4+3] = v3;
            sum += v0 + v1 + v2 + v3;
        }
        float mean = warpAll(sum) * (1.f / 512.f);
        float vs = 0.f;
        #pragma unroll
        for (int i = 0; i < 16; i++) {
            float d = x[i] - mean;
            x[i] = d;
            vs += d * d;
        }
        float inv = rsqrtf(warpAll(vs) * (1.f / 512.f) + 1e-5f);
        __half* dr = g_Hh + ((long)b * S_ + s) * D_;
        #pragma unroll
        for (int i = 0; i < 4; i++) {
            int base = i * 128 + lane * 4;
            float o0 = x[i*4+0] * inv * s_g[base + 0] + s_b[base + 0];
            float o1 = x[i*4+1] * inv * s_g[base + 1] + s_b[base + 1];
            float o2 = x[i*4+2] * inv * s_g[base + 2] + s_b[base + 2];
            float o3 = x[i*4+3] * inv * s_g[base + 3] + s_b[base + 3];
            __half2 ha = __floats2half2_rn(o0, o1);
            __half2 hb = __floats2half2_rn(o2, o3);
            *(__half2*)(dr + base)     = ha;
            *(__half2*)(dr + base + 2) = hb;
        }
    }
}

// ---------------- fused attention v5: chunk-split x2, WMMA scores + ctx --------
__global__ __launch_bounds__(256) void k_attn(
    const float* __restrict__ bk, const float* __restrict__ bq,
    const int* __restrict__ stc)
{
    pdl_sync();
    int b = blockIdx.x;
    int part = blockIdx.y;                 // 0 or 1: chunk-split
    int tid = threadIdx.x, lane = tid & 31, warp = tid >> 5;   // 8 warps
    extern __shared__ __align__(16) char asm_[];
    __half* Hs   = (__half*)(asm_ + AOFF_HS);    // 32 x 520 half
    __half* uKh  = (__half*)(asm_ + AOFF_UKH);   // 8 x 520 half
    __half* uKl  = (__half*)(asm_ + AOFF_UKL);
    float* scb   = (float*)(asm_ + AOFF_SC);     // 8 x 256 (warp scratch)
    float* ps    = (float*)(asm_ + AOFF_PS);     // 32 x 8
    __half* psTh = (__half*)(asm_ + AOFF_PTH);   // 8 x 40 half
    __half* psTl = (__half*)(asm_ + AOFF_PTL);
    float* cKs   = (float*)(asm_ + AOFF_CK);
    float* pss   = (float*)(asm_ + AOFF_PSS);
    int len = stc[b];

    // stage uK -> half hi/lo (8 rows)
    {
        const float* src = g_uK + (long)b * NH_ * D_;
        #pragma unroll
        for (int i = 0; i < 16; i++) {
            int idx = tid + i * 256;
            int h = idx >> 9, k = idx & 511;
            float v = src[idx];
            __half hh = __float2half(v);
            uKh[h * AHS_ROW + k] = hh;
            uKl[h * AHS_ROW + k] = __float2half(v - __half2float(hh));
        }
    }
    // cK[h] = bk_h . q_h (q composed from comb partials + bq)
    {
        int j0 = warp * 64 + lane, j1 = j0 + 32;
        float q0 = g_partC[(long)b * 2048 + j0] + g_partC[PC1_OFF + (long)b * 2048 + j0] + bq[j0];
        float q1 = g_partC[(long)b * 2048 + j1] + g_partC[PC1_OFF + (long)b * 2048 + j1] + bq[j1];
        float v = bk[j0] * q0 + bk[j1] * q1;
        v = warpSum(v);
        if (lane == 0) { cKs[warp] = v; pss[warp] = 0.f; }
    }
    // persistent ctx accumulators: warp owns n-cols [warp*64, warp*64+64)
    nvcuda::wmma::fragment<nvcuda::wmma::accumulator, 8, 32, 16, float> cacc[2];
    #pragma unroll
    for (int j = 0; j < 2; j++) nvcuda::wmma::fill_fragment(cacc[j], 0.0f);
    __syncthreads();

    int nch = (len + CH - 1) / CH;
    for (int c = part; c < nch; c += 2) {
        int s0 = c * CH;
        // stage H chunk as raw half rows (zero past len)
        for (int r = warp; r < CH; r += 8) {
            int s = s0 + r;
            uint4* dst = (uint4*)(Hs + r * AHS_ROW);
            if (s < len) {
                const uint4* src = (const uint4*)(g_Hh + ((long)b * S_ + s) * D_);
                dst[lane] = src[lane];
                dst[lane + 32] = src[lane + 32];
            } else {
                uint4 z; z.x = 0; z.y = 0; z.z = 0; z.w = 0;
                dst[lane] = z;
                dst[lane + 32] = z;
            }
        }
        __syncthreads();
        // scores via WMMA m32n8k16: (32 x 512) @ (512 x 8), k split across warps
        {
            nvcuda::wmma::fragment<nvcuda::wmma::accumulator, 32, 8, 16, float> sacc;
            nvcuda::wmma::fill_fragment(sacc, 0.0f);
            #pragma unroll
            for (int kt = 0; kt < 4; kt++) {
                int k0 = (warp * 4 + kt) * 16;
                nvcuda::wmma::fragment<nvcuda::wmma::matrix_a, 32, 8, 16,
                                       __half, nvcuda::wmma::row_major> af;
                nvcuda::wmma::fragment<nvcuda::wmma::matrix_b, 32, 8, 16,
                                       __half, nvcuda::wmma::col_major> bfh, bfl;
                nvcuda::wmma::load_matrix_sync(af, Hs + k0, AHS_ROW);
                nvcuda::wmma::load_matrix_sync(bfh, uKh + k0, AHS_ROW);
                nvcuda::wmma::load_matrix_sync(bfl, uKl + k0, AHS_ROW);
                nvcuda::wmma::mma_sync(sacc, af, bfh, sacc);
                nvcuda::wmma::mma_sync(sacc, af, bfl, sacc);
            }
            nvcuda::wmma::store_matrix_sync(scb + warp * 256, sacc, 8,
                                            nvcuda::wmma::mem_row_major);
        }
        __syncthreads();
        // combine warp partials + sigmoid -> ps and psT hi/lo
        {
            int r = tid >> 3, h = tid & 7;
            float v = 0.f;
            #pragma unroll
            for (int w = 0; w < 8; w++) v += scb[w * 256 + r * 8 + h];
            int s = s0 + r;
            float p = (s < len) ? sigm(0.125f * (v + cKs[h])) : 0.f;
            ps[r * NH_ + h] = p;
            __half ph = __float2half(p);
            psTh[h * APT_ROW + r] = ph;
            psTl[h * APT_ROW + r] = __float2half(p - __half2float(ph));
        }
        __syncthreads();
        // ctx via WMMA m8n32k16: P^T(8x32 hi/lo) @ Hs(32x512)
        #pragma unroll
        for (int kt = 0; kt < 2; kt++) {
            nvcuda::wmma::fragment<nvcuda::wmma::matrix_a, 8, 32, 16,
                                   __half, nvcuda::wmma::row_major> pah, pal;
            nvcuda::wmma::load_matrix_sync(pah, psTh + kt * 16, APT_ROW);
            nvcuda::wmma::load_matrix_sync(pal, psTl + kt * 16, APT_ROW);
            #pragma unroll
            for (int j = 0; j < 2; j++) {
                nvcuda::wmma::fragment<nvcuda::wmma::matrix_b, 8, 32, 16,
                                       __half, nvcuda::wmma::row_major> hb;
                nvcuda::wmma::load_matrix_sync(hb, Hs + kt * 16 * AHS_ROW + warp * 64 + j * 32,
                                               AHS_ROW);
                nvcuda::wmma::mma_sync(cacc[j], pah, hb, cacc[j]);
                nvcuda::wmma::mma_sync(cacc[j], pal, hb, cacc[j]);
            }
        }
        // psum
        {
            float v = ps[lane * NH_ + warp];
            v = warpSum(v);
            if (lane == 0) pss[warp] += v;
        }
        __syncthreads();
    }
    // drain ctx accumulators into this part's slot
    float* ctxDst = g_ctx + (long)part * CTX_OFF;
    #pragma unroll
    for (int j = 0; j < 2; j++) {
        nvcuda::wmma::store_matrix_sync(scb + warp * 256, cacc[j], 32,
                                        nvcuda::wmma::mem_row_major);
        __syncwarp();
        int h = lane >> 2;
        int cb = (lane & 3) * 8;
        float4 v0;
        v0.x = scb[warp * 256 + h * 32 + cb + 0];
        v0.y = scb[warp * 256 + h * 32 + cb + 1];
        v0.z = scb[warp * 256 + h * 32 + cb + 2];
        v0.w = scb[warp * 256 + h * 32 + cb + 3];
        float4 v1;
        v1.x = scb[warp * 256 + h * 32 + cb + 4];
        v1.y = scb[warp * 256 + h * 32 + cb + 5];
        v1.z = scb[warp * 256 + h * 32 + cb + 6];
        v1.w = scb[warp * 256 + h * 32 + cb + 7];
        long o = ((long)b * NH_ + h) * D_ + warp * 64 + j * 32 + cb;
        *(float4*)&ctxDst[o] = v0;
        *(float4*)&ctxDst[o + 4] = v1;
        __syncwarp();
    }
    if (tid < NH_) g_psum[part * PS1_OFF + b * NH_ + tid] = pss[tid];
}

// ---------------- small per-iter kernels --------------------------------------
__global__ __launch_bounds__(512) void k_ln_mt(
    const float* __restrict__ bv, const float* __restrict__ lng_g,
    const float* __restrict__ lng_b)
{
    pdl_sync();
    int b = blockIdx.x, t = threadIdx.x;
    __shared__ float red[32];
    long o = (long)b * 512 + t;
    float psum = g_psum[b * NH_ + (t >> 6)] + g_psum[PS1_OFF + b * NH_ + (t >> 6)];
    float x = g_partM[o] + g_partM[PM_OFF + o] + g_partM[2 * PM_OFF + o]
            + g_partM[3 * PM_OFF + o] + psum * bv[t];
    float mean = blockSum(x, red) * (1.f / 512.f);
    float d = x - mean;
    float var = blockSum(d * d, red) * (1.f / 512.f);
    g_mt[b * D_ + t] = d * rsqrtf(var + 1e-5f) * lng_g[t] + lng_b[t];
}

__global__ __launch_bounds__(512) void k_gru(
    const float* __restrict__ b_ih, const float* __restrict__ b_hh,
    float* __restrict__ out, int last)
{
    int b = blockIdx.x, t = threadIdx.x;
    const float* G0 = g_partG + (long)b * 1536;
    const float* G1 = g_partG + PG1_OFF + (long)b * 1536;
    const float* C0 = g_partC + (long)b * 2048 + 512;
    const float* C1 = g_partC + PC1_OFF + (long)b * 2048 + 512;
    float ir = G0[t]        + G1[t]        + b_ih[t];
    float iz = G0[t + 512]  + G1[t + 512]  + b_ih[t + 512];
    float in = G0[t + 1024] + G1[t + 1024] + b_ih[t + 1024];
    float hr = C0[t]        + C1[t]        + b_hh[t];
    float hz = C0[t + 512]  + C1[t + 512]  + b_hh[t + 512];
    float hn = C0[t + 1024] + C1[t + 1024] + b_hh[t + 1024];
    float r = sigm(ir + hr);
    float z = sigm(iz + hz);
    float n = tanhf(in + r * hn);
    float old = g_bt[b * D_ + t];
    float nv = (1.f - z) * n + z * old;
    g_bt[b * D_ + t] = nv;
    if (last) out[b * 512 + t] = nv;
}

// ---------------- launch --------------------------------------------------------
extern "C" void kernel_launch(void* const* d_in, const int* in_sizes, int n_in,
                              void* d_out, int out_size)
{
    const float* emb   = (const float*)d_in[0];
    const int*   stc   = (const int*)  d_in[1];
    const int*   off   = (const int*)  d_in[2];
    const int*   sep   = (const int*)  d_in[3];
    const float* W1    = (const float*)d_in[4];
    const float* W2    = (const float*)d_in[5];
    const float* ln_g  = (const float*)d_in[6];
    const float* ln_b  = (const float*)d_in[7];
    const float* lng_g = (const float*)d_in[8];
    const float* lng_b = (const float*)d_in[9];
    const float* Wq    = (const float*)d_in[10];
    const float* bq    = (const float*)d_in[11];
    const float* Wk    = (const float*)d_in[12];
    const float* bk    = (const float*)d_in[13];
    const float* Wv    = (const float*)d_in[14];
    const float* bv    = (const float*)d_in[15];
    const float* W_ih  = (const float*)d_in[16];
    const float* W_hh  = (const float*)d_in[17];
    const float* b_ih  = (const float*)d_in[18];
    const float* b_hh  = (const float*)d_in[19];
    const float* seg   = (const float*)d_in[20];
    const float* pe    = (const float*)d_in[21];
    float* out = (float*)d_out;

    cudaFuncSetAttribute(k_attn, cudaFuncAttributeMaxDynamicSharedMemorySize, ATTN_SMEM_V5);
    cudaFuncSetAttribute(k_tc_w1,   cudaFuncAttributeMaxDynamicSharedMemorySize, SMEM_TCB128);
    cudaFuncSetAttribute(k_tc_q,    cudaFuncAttributeMaxDynamicSharedMemorySize, SMEM_TCB128);
    cudaFuncSetAttribute(k_tc_gh,   cudaFuncAttributeMaxDynamicSharedMemorySize, SMEM_TCB128);
    cudaFuncSetAttribute(k_tc_uk,   cudaFuncAttributeMaxDynamicSharedMemorySize, SMEM_TCB128);
    cudaFuncSetAttribute(k_tc_gi,   cudaFuncAttributeMaxDynamicSharedMemorySize, SMEM_TCB128);
    cudaFuncSetAttribute(k_tc_mraw, cudaFuncAttributeMaxDynamicSharedMemorySize, SMEM_TCB64);

    cudaStream_t sB;
    cudaStreamCreateWithFlags(&sB, cudaStreamNonBlocking);
    cudaEvent_t evF, evH, evG;
    cudaEventCreateWithFlags(&evF, cudaEventDisableTiming);
    cudaEventCreateWithFlags(&evH, cudaEventDisableTiming);
    cudaEventCreateWithFlags(&evG, cudaEventDisableTiming);

    cudaLaunchAttribute pdlAttr[1];
    pdlAttr[0].id = cudaLaunchAttributeProgrammaticStreamSerialization;
    pdlAttr[0].val.programmaticStreamSerializationAllowed = 1;
    auto mkcfg = [&](dim3 g, dim3 b, size_t smem) {
        cudaLaunchConfig_t c;
        c.gridDim = g; c.blockDim = b; c.dynamicSmemBytes = smem;
        c.stream = 0; c.attrs = pdlAttr; c.numAttrs = 1;
        return c;
    };

    // ---- preamble: side stream does non-critical weight prep + buildH ----
    cudaEventRecord(evF, 0);
    cudaStreamWaitEvent(sB, evF, 0);
    k_prep<<<dim3(16, 48, 5), 256, 0, sB>>>(Wk, W_ih, W_hh, Wq, Wv, W1, 0);
    k_buildH<<<B_, 256, 0, sB>>>(emb, pe, seg, ln_g, ln_b, stc, off);
    cudaEventRecord(evH, sB);

    // critical preamble chain: W1 split -> hblk -> W1 GEMM -> a -> s1 -> b0
    k_prep<<<dim3(16, 16, 1), 256>>>(Wk, W_ih, W_hh, Wq, Wv, W1, 5);
    {
        cudaLaunchConfig_t c = mkcfg(dim3(B_, 1, 1), dim3(512, 1, 1), 0);
        cudaLaunchKernelEx(&c, k_build_hblk, emb, stc, off, sep);
    }
    {
        cudaLaunchConfig_t c = mkcfg(dim3(4, 32, 2), dim3(256, 1, 1), SMEM_TCB128);
        cudaLaunchKernelEx(&c, k_tc_w1);
    }
    {
        cudaLaunchConfig_t c = mkcfg(dim3(2048, 1, 1), dim3(256, 1, 1), 0);
        cudaLaunchKernelEx(&c, k_a, W2);
    }
    {
        cudaLaunchConfig_t c = mkcfg(dim3(L_, 1, 1), dim3(512, 1, 1), 0);
        cudaLaunchKernelEx(&c, k_s1);
    }
    {
        cudaLaunchConfig_t c = mkcfg(dim3(B_, 1, 1), dim3(512, 1, 1), 0);
        cudaLaunchKernelEx(&c, k_b0, ln_g, ln_b, pe);
    }
    // join side stream: weights + H ready before first iteration GEMMs
    cudaStreamWaitEvent(0, evH, 0);

    // ---- 3 GRU iterations ----
    for (int it = 0; it < 3; it++) {
        cudaEventRecord(evF, 0);
        cudaStreamWaitEvent(sB, evF, 0);
        k_tc_gh<<<dim3(12, 8, 2), 256, SMEM_TCB128, sB>>>();
        cudaEventRecord(evG, sB);

        {
            cudaLaunchConfig_t c = mkcfg(dim3(4, 8, 2), dim3(256, 1, 1), SMEM_TCB128);
            cudaLaunchKernelEx(&c, k_tc_q);
        }
        {
            cudaLaunchConfig_t c = mkcfg(dim3(4, 8, 8), dim3(256, 1, 1), SMEM_TCB128);
            cudaLaunchKernelEx(&c, k_tc_uk, bq);
        }
        {
            cudaLaunchConfig_t c = mkcfg(dim3(B_, 2, 1), dim3(256, 1, 1), ATTN_SMEM_V5);
            cudaLaunchKernelEx(&c, k_attn, bk, bq, stc);
        }
        {
            cudaLaunchConfig_t c = mkcfg(dim3(1, 8, 32), dim3(256, 1, 1), SMEM_TCB64);
            cudaLaunchKernelEx(&c, k_tc_mraw);
        }
        {
            cudaLaunchConfig_t c = mkcfg(dim3(B_, 1, 1), dim3(512, 1, 1), 0);
            cudaLaunchKernelEx(&c, k_ln_mt, bv, lng_g, lng_b);
        }
        {
            cudaLaunchConfig_t c = mkcfg(dim3(12, 8, 2), dim3(256, 1, 1), SMEM_TCB128);
            cudaLaunchKernelEx(&c, k_tc_gi);
        }
        cudaStreamWaitEvent(0, evG, 0);
        k_gru<<<B_, 512>>>(b_ih, b_hh, out, it == 2 ? 1 : 0);
    }
    (void)in_sizes; (void)n_in; (void)out_size;
}

// round 17
// speedup vs baseline: 1.0062x; 1.0062x over previous
#include <cuda_runtime.h>
#include <cuda_bf16.h>
#include <cuda_fp16.h>
#include <cuda_pipeline.h>
#include <mma.h>
#include <math.h>

#define B_  512
#define S_  200
#define D_  512
#define NH_ 8
#define L_  4
#define CH  32

// ---------------- scratch (device globals) ----------------------------------
__device__ float g_hblk[B_*L_*D_];
__device__ float g_valid[B_*L_];
__device__ float g_a[B_*L_];
__device__ float g_s1[B_*L_];
__device__ float g_bt[B_*D_];
__device__ __half g_Hh[B_*S_*D_];        // 105 MB (fp16 H)
__device__ float g_uK[B_*NH_*D_];
__device__ float g_ctx[B_*NH_*D_];
__device__ float g_psum[B_*NH_];
__device__ float g_mt[B_*D_];
__device__ float g_partC[2*B_*2048];     // comb / W1 split-K partials
__device__ float g_partM[4*B_*D_];       // mraw split-K partials
__device__ float g_partG[2*B_*1536];     // gi split-K partials

// bf16 hi/lo split weights, [N][K] layout (K contiguous)
__device__ __nv_bfloat16 g_combT_h[2048*512];
__device__ __nv_bfloat16 g_combT_l[2048*512];
__device__ __nv_bfloat16 g_Wih_h[1536*512];
__device__ __nv_bfloat16 g_Wih_l[1536*512];
__device__ __nv_bfloat16 g_Wk_h[512*512];
__device__ __nv_bfloat16 g_Wk_l[512*512];
__device__ __nv_bfloat16 g_WvT_h[512*512];
__device__ __nv_bfloat16 g_WvT_l[512*512];
__device__ __nv_bfloat16 g_W1T_h[512*512];
__device__ __nv_bfloat16 g_W1T_l[512*512];

#define PC1_OFF 1048576L   // 512*2048
#define PM_OFF  262144L    // 512*512
#define PG1_OFF 786432L    // 512*1536

// dynamic smem: 2 stages x (A(64) h/l + B(BN) h/l) x RS(40) x 2B
#define SMEM_TCB128 61440
#define SMEM_TCB64  40960

// attention v4 smem layout (bytes)
#define AHS_ROW   520                       // halfs per Hs row (512 + 8 pad)
#define APT_ROW   40                        // halfs per psT row (32 + 8 pad)
#define AOFF_HS   0                         // 32 x 520 half = 33280
#define AOFF_UKH  33280                     // 8 x 520 half = 8320
#define AOFF_UKL  41600                     // 8 x 520 half = 8320
#define AOFF_SC   49920                     // 8 x 256 float = 8192
#define AOFF_PS   58112                     // 32 x 8 float = 1024
#define AOFF_PTH  59136                     // 8 x 40 half = 640
#define AOFF_PTL  59776                     // 8 x 40 half = 640
#define AOFF_CK   60416                     // 8 float
#define AOFF_PSS  60448                     // 8 float
#define ATTN_SMEM_V4 60480

// PDL helpers
__device__ __forceinline__ void pdl_sync() {
#if __CUDA_ARCH__ >= 900
    cudaGridDependencySynchronize();
    cudaTriggerProgrammaticLaunchCompletion();
#endif
}

// ---------------- helpers ----------------------------------------------------
__device__ __forceinline__ float warpSum(float v) {
    #pragma unroll
    for (int o = 16; o; o >>= 1) v += __shfl_down_sync(0xffffffffu, v, o);
    return v;
}
__device__ __forceinline__ float warpAll(float v) {
    #pragma unroll
    for (int o = 16; o; o >>= 1) v += __shfl_xor_sync(0xffffffffu, v, o);
    return v;
}
__device__ __forceinline__ float warpMax(float v) {
    #pragma unroll
    for (int o = 16; o; o >>= 1) v = fmaxf(v, __shfl_down_sync(0xffffffffu, v, o));
    return v;
}
__device__ __forceinline__ float blockSum(float v, float* red) {
    int lane = threadIdx.x & 31, w = threadIdx.x >> 5;
    v = warpSum(v);
    if (lane == 0) red[w] = v;
    __syncthreads();
    float r = 0.f;
    if (threadIdx.x < (blockDim.x >> 5)) r = red[threadIdx.x];
    if (w == 0) r = warpSum(r);
    if (threadIdx.x == 0) red[0] = r;
    __syncthreads();
    r = red[0];
    __syncthreads();
    return r;
}
__device__ __forceinline__ float blockMax(float v, float* red) {
    int lane = threadIdx.x & 31, w = threadIdx.x >> 5;
    v = warpMax(v);
    if (lane == 0) red[w] = v;
    __syncthreads();
    float r = -3.0e38f;
    if (threadIdx.x < (blockDim.x >> 5)) r = red[threadIdx.x];
    if (w == 0) r = warpMax(r);
    if (threadIdx.x == 0) red[0] = r;
    __syncthreads();
    r = red[0];
    __syncthreads();
    return r;
}
__device__ __forceinline__ float sigm(float x) { return 1.f / (1.f + expf(-x)); }

// ---------------- WMMA tensor GEMM core v2 (unchanged from R15) ----------------
template <int BN, bool COMPOSE>
__device__ __forceinline__ void tc_core(
    const float* A0, const float* A1, const float* Ab, int lda,
    const __nv_bfloat16* Bh, const __nv_bfloat16* Bl, int ldb,
    float* C, int ldc, int Kd, int m0, int n0)
{
    const int RS = 40;
    const int NT = BN / 64;
    const int BCH = BN / 64;
    const int AE = 64 * RS;
    const int BE = BN * RS;
    const int STG = 2 * AE + 2 * BE;

    extern __shared__ __align__(16) __nv_bfloat16 dsm[];

    pdl_sync();

    int tid = threadIdx.x;
    int warp = tid >> 5;
    int wm = warp & 1;
    int wn = warp >> 1;

    nvcuda::wmma::fragment<nvcuda::wmma::accumulator, 16, 16, 16, float> acc[2][NT];
    #pragma unroll
    for (int i = 0; i < 2; i++) {
        #pragma unroll
        for (int j = 0; j < NT; j++) {
            nvcuda::wmma::fill_fragment(acc[i][j], 0.0f);
        }
    }

    float4 va[2];
    int arow = tid >> 3;
    int aq = tid & 7;

    {
        __nv_bfloat16* sBh = dsm + 2 * AE;
        __nv_bfloat16* sBl = dsm + 2 * AE + BE;
        #pragma unroll
        for (int i = 0; i < BCH; i++) {
            int c = tid + i * 256;
            int row = c >> 2;
            int q = c & 3;
            __pipeline_memcpy_async(sBh + row * RS + q * 8,
                                    Bh + (long)(n0 + row) * ldb + q * 8, 16);
            __pipeline_memcpy_async(sBl + row * RS + q * 8,
                                    Bl + (long)(n0 + row) * ldb + q * 8, 16);
        }
        __pipeline_commit();
        #pragma unroll
        for (int i = 0; i < 2; i++) {
            int row = arow + i * 32;
            float4 v = *(const float4*)(A0 + (long)(m0 + row) * lda + aq * 4);
            if (COMPOSE) {
                float4 v1 = *(const float4*)(A1 + (long)(m0 + row) * lda + aq * 4);
                float4 bi = *(const float4*)(Ab + aq * 4);
                v.x += v1.x + bi.x; v.y += v1.y + bi.y;
                v.z += v1.z + bi.z; v.w += v1.w + bi.w;
            }
            va[i] = v;
        }
        __nv_bfloat16* sAh = dsm;
        __nv_bfloat16* sAl = dsm + AE;
        #pragma unroll
        for (int i = 0; i < 2; i++) {
            int row = arow + i * 32;
            float4 v = va[i];
            __nv_bfloat16 h0 = __float2bfloat16(v.x);
            __nv_bfloat16 h1 = __float2bfloat16(v.y);
            __nv_bfloat16 h2 = __float2bfloat16(v.z);
            __nv_bfloat16 h3 = __float2bfloat16(v.w);
            int o = row * RS + aq * 4;
            sAh[o + 0] = h0; sAh[o + 1] = h1; sAh[o + 2] = h2; sAh[o + 3] = h3;
            sAl[o + 0] = __float2bfloat16(v.x - __bfloat162float(h0));
            sAl[o + 1] = __float2bfloat16(v.y - __bfloat162float(h1));
            sAl[o + 2] = __float2bfloat16(v.z - __bfloat162float(h2));
            sAl[o + 3] = __float2bfloat16(v.w - __bfloat162float(h3));
        }
        __pipeline_wait_prior(0);
        __syncthreads();
    }

    int nch = Kd >> 5;
    for (int c = 0; c < nch; c++) {
        int kn = (c + 1) * 32;
        __nv_bfloat16* nxt = dsm + ((c + 1) & 1) * STG;
        if (c + 1 < nch) {
            __nv_bfloat16* sBh = nxt + 2 * AE;
            __nv_bfloat16* sBl = nxt + 2 * AE + BE;
            #pragma unroll
            for (int i = 0; i < BCH; i++) {
                int cc = tid + i * 256;
                int row = cc >> 2;
                int q = cc & 3;
                __pipeline_memcpy_async(sBh + row * RS + q * 8,
                                        Bh + (long)(n0 + row) * ldb + kn + q * 8, 16);
                __pipeline_memcpy_async(sBl + row * RS + q * 8,
                                        Bl + (long)(n0 + row) * ldb + kn + q * 8, 16);
            }
            __pipeline_commit();
            #pragma unroll
            for (int i = 0; i < 2; i++) {
                int row = arow + i * 32;
                float4 v = *(const float4*)(A0 + (long)(m0 + row) * lda + kn + aq * 4);
                if (COMPOSE) {
                    float4 v1 = *(const float4*)(A1 + (long)(m0 + row) * lda + kn + aq * 4);
                    float4 bi = *(const float4*)(Ab + kn + aq * 4);
                    v.x += v1.x + bi.x; v.y += v1.y + bi.y;
                    v.z += v1.z + bi.z; v.w += v1.w + bi.w;
                }
                va[i] = v;
            }
        }
        {
            __nv_bfloat16* base = dsm + (c & 1) * STG;
            __nv_bfloat16* sAh = base;
            __nv_bfloat16* sAl = base + AE;
            __nv_bfloat16* sBh = base + 2 * AE;
            __nv_bfloat16* sBl = base + 2 * AE + BE;
            #pragma unroll
            for (int ks = 0; ks < 2; ks++) {
                nvcuda::wmma::fragment<nvcuda::wmma::matrix_a, 16, 16, 16,
                                       __nv_bfloat16, nvcuda::wmma::row_major> ah[2], al[2];
                #pragma unroll
                for (int i = 0; i < 2; i++) {
                    int r = wm * 32 + i * 16;
                    nvcuda::wmma::load_matrix_sync(ah[i], sAh + r * RS + ks * 16, RS);
                    nvcuda::wmma::load_matrix_sync(al[i], sAl + r * RS + ks * 16, RS);
                }
                #pragma unroll
                for (int j = 0; j < NT; j++) {
                    int nn = wn * (BN / 4) + j * 16;
                    nvcuda::wmma::fragment<nvcuda::wmma::matrix_b, 16, 16, 16,
                                           __nv_bfloat16, nvcuda::wmma::col_major> bh, bl;
                    nvcuda::wmma::load_matrix_sync(bh, sBh + nn * RS + ks * 16, RS);
                    nvcuda::wmma::load_matrix_sync(bl, sBl + nn * RS + ks * 16, RS);
                    #pragma unroll
                    for (int i = 0; i < 2; i++) {
                        nvcuda::wmma::mma_sync(acc[i][j], ah[i], bh, acc[i][j]);
                        nvcuda::wmma::mma_sync(acc[i][j], ah[i], bl, acc[i][j]);
                        nvcuda::wmma::mma_sync(acc[i][j], al[i], bh, acc[i][j]);
                    }
                }
            }
        }
        if (c + 1 < nch) {
            __nv_bfloat16* sAh = nxt;
            __nv_bfloat16* sAl = nxt + AE;
            #pragma unroll
            for (int i = 0; i < 2; i++) {
                int row = arow + i * 32;
                float4 v = va[i];
                __nv_bfloat16 h0 = __float2bfloat16(v.x);
                __nv_bfloat16 h1 = __float2bfloat16(v.y);
                __nv_bfloat16 h2 = __float2bfloat16(v.z);
                __nv_bfloat16 h3 = __float2bfloat16(v.w);
                int o = row * RS + aq * 4;
                sAh[o + 0] = h0; sAh[o + 1] = h1; sAh[o + 2] = h2; sAh[o + 3] = h3;
                sAl[o + 0] = __float2bfloat16(v.x - __bfloat162float(h0));
                sAl[o + 1] = __float2bfloat16(v.y - __bfloat162float(h1));
                sAl[o + 2] = __float2bfloat16(v.z - __bfloat162float(h2));
                sAl[o + 3] = __float2bfloat16(v.w - __bfloat162float(h3));
            }
            __pipeline_wait_prior(0);
        }
        __syncthreads();
    }
    #pragma unroll
    for (int i = 0; i < 2; i++) {
        #pragma unroll
        for (int j = 0; j < NT; j++) {
            int row = m0 + wm * 32 + i * 16;
            int col = n0 + wn * (BN / 4) + j * 16;
            nvcuda::wmma::store_matrix_sync(C + (long)row * ldc + col, acc[i][j],
                                            ldc, nvcuda::wmma::mem_row_major);
        }
    }
}

// ---------------- GEMM wrapper kernels (BM=64, 2 CTAs/SM) ----------------------
__global__ __launch_bounds__(256, 2) void k_tc_w1()
{
    int z = blockIdx.z;
    tc_core<128, false>(g_hblk + z * 256, (const float*)0, (const float*)0, 512,
                        g_W1T_h + z * 256, g_W1T_l + z * 256, 512,
                        g_partC + (long)z * PC1_OFF, 512, 256,
                        blockIdx.y * 64, blockIdx.x * 128);
}
// q partials: BN=64 tiles for 2x CTA parallelism (128 CTAs)
__global__ __launch_bounds__(256, 2) void k_tc_q()
{
    int z = blockIdx.z;
    tc_core<64, false>(g_bt + z * 256, (const float*)0, (const float*)0, 512,
                       g_combT_h + z * 256, g_combT_l + z * 256, 512,
                       g_partC + (long)z * PC1_OFF, 2048, 256,
                       blockIdx.y * 64, blockIdx.x * 64);
}
__global__ __launch_bounds__(256, 2) void k_tc_gh()
{
    int z = blockIdx.z;
    tc_core<128, false>(g_bt + z * 256, (const float*)0, (const float*)0, 512,
                        g_combT_h + (long)512 * 512 + z * 256,
                        g_combT_l + (long)512 * 512 + z * 256, 512,
                        g_partC + (long)z * PC1_OFF + 512, 2048, 256,
                        blockIdx.y * 64, blockIdx.x * 128);
}
__global__ __launch_bounds__(256, 2) void k_tc_uk(const float* __restrict__ bq)
{
    int h = blockIdx.z;
    tc_core<128, true>(g_partC + h * 64, g_partC + PC1_OFF + h * 64, bq + h * 64, 2048,
                       g_Wk_h + h * 64, g_Wk_l + h * 64, 512,
                       g_uK + h * 512, 4096, 64,
                       blockIdx.y * 64, blockIdx.x * 128);
}
__global__ __launch_bounds__(256, 2) void k_tc_mraw()
{
    int z = blockIdx.z;
    int h = z >> 2;
    int ks = z & 3;
    tc_core<64, false>(g_ctx + h * 512 + (long)ks * 128, (const float*)0, (const float*)0, 4096,
                       g_WvT_h + (long)(h * 64) * 512 + ks * 128,
                       g_WvT_l + (long)(h * 64) * 512 + ks * 128, 512,
                       g_partM + ks * PM_OFF + h * 64, 512, 128,
                       blockIdx.y * 64, 0);
}
__global__ __launch_bounds__(256, 2) void k_tc_gi()
{
    int z = blockIdx.z;
    tc_core<128, false>(g_mt + z * 256, (const float*)0, (const float*)0, 512,
                        g_Wih_h + z * 256, g_Wih_l + z * 256, 512,
                        g_partG + (long)z * PG1_OFF, 1536, 256,
                        blockIdx.y * 64, blockIdx.x * 128);
}

// ---------------- weight prep (jbase selects job subset) -----------------------
__global__ __launch_bounds__(256) void k_prep(
    const float* __restrict__ Wk, const float* __restrict__ W_ih,
    const float* __restrict__ W_hh, const float* __restrict__ Wq,
    const float* __restrict__ Wv, const float* __restrict__ W1, int jbase)
{
    __shared__ float t[32][33];
    int job = blockIdx.z + jbase;
    int bx = blockIdx.x * 32;
    int by = blockIdx.y * 32;
    int lx = threadIdx.x & 31;
    int wy = threadIdx.x >> 5;
    if (job <= 2) {
        const float* src;
        __nv_bfloat16* dh;
        __nv_bfloat16* dl;
        int nrows;
        if (job == 0)      { src = Wk;   dh = g_Wk_h;  dl = g_Wk_l;  nrows = 512;  }
        else if (job == 1) { src = W_ih; dh = g_Wih_h; dl = g_Wih_l; nrows = 1536; }
        else               { src = W_hh; dh = g_combT_h + 512*512;
                             dl = g_combT_l + 512*512; nrows = 1536; }
        if (by >= nrows) return;
        for (int j = wy; j < 32; j += 8) {
            long o = (long)(by + j) * 512 + bx + lx;
            float v = src[o];
            __nv_bfloat16 hh = __float2bfloat16(v);
            dh[o] = hh;
            dl[o] = __float2bfloat16(v - __bfloat162float(hh));
        }
    } else {
        if (blockIdx.y >= 16) return;
        const float* src;
        __nv_bfloat16* dh;
        __nv_bfloat16* dl;
        if (job == 3)      { src = Wq; dh = g_combT_h; dl = g_combT_l; }
        else if (job == 4) { src = Wv; dh = g_WvT_h;   dl = g_WvT_l;   }
        else               { src = W1; dh = g_W1T_h;   dl = g_W1T_l;   }
        for (int j = wy; j < 32; j += 8)
            t[j][lx] = src[(long)(by + j) * 512 + bx + lx];
        __syncthreads();
        for (int j = wy; j < 32; j += 8) {
            float v = t[lx][j];
            long o = (long)(bx + j) * 512 + by + lx;
            __nv_bfloat16 hh = __float2bfloat16(v);
            dh[o] = hh;
            dl[o] = __float2bfloat16(v - __bfloat162float(hh));
        }
    }
}

// ---------------- preamble -----------------------------------------------------
__global__ __launch_bounds__(512) void k_build_hblk(
    const float* __restrict__ emb, const int* __restrict__ stc,
    const int* __restrict__ off, const int* __restrict__ sep)
{
    pdl_sync();
    int b = blockIdx.x;
    int o = off[b], len = stc[b];
    int sA = sep[b * 2], sB2 = sep[b * 2 + 1];
    int idx = (sA < o ? 1 : 0) + (sB2 < o ? 1 : 0);
    int pidx = idx - 1; pidx = pidx < 0 ? 0 : (pidx > 1 ? 1 : pidx);
    int prev = (pidx == 0) ? sA : sB2;
    int left = (idx > 0) ? prev + 1 : 0;
    int nidx = idx > 1 ? 1 : idx;
    int nxt = (nidx == 0) ? sA : sB2;
    int right = (idx < 2) ? nxt : len;
    int start = (o - 2 > left) ? o - 2 : left;
    int end = (o + 2 < right) ? o + 2 : right;
    int t = threadIdx.x;
    #pragma unroll
    for (int l = 0; l < L_; l++) {
        int ind = start + l;
        bool v = ind < end;
        int ic = ind < 0 ? 0 : (ind > S_ - 1 ? S_ - 1 : ind);
        g_hblk[(b * L_ + l) * D_ + t] = v ? emb[((long)b * S_ + ic) * D_ + t] : 0.f;
        if (t == 0) g_valid[b * L_ + l] = v ? 1.f : 0.f;
    }
}

__global__ __launch_bounds__(256) void k_a(const float* __restrict__ W2)
{
    pdl_sync();
    int m = blockIdx.x, t = threadIdx.x;
    float t0 = tanhf(g_partC[(long)m * 512 + t] + g_partC[PC1_OFF + (long)m * 512 + t]);
    float t1 = tanhf(g_partC[(long)m * 512 + t + 256] + g_partC[PC1_OFF + (long)m * 512 + t + 256]);
    float v = t0 * W2[t] + t1 * W2[t + 256];
    __shared__ float red[32];
    v = blockSum(v, red);
    if (t == 0) g_a[m] = v;
}

__global__ __launch_bounds__(512) void k_s1()
{
    pdl_sync();
    int l = blockIdx.x, t = threadIdx.x;
    __shared__ float red[32];
    float v = g_a[t * L_ + l];
    float mx = blockMax(v, red);
    float e = expf(v - mx);
    float s = blockSum(e, red);
    g_s1[t * L_ + l] = e / s;
}

__global__ __launch_bounds__(512) void k_b0(
    const float* __restrict__ ln_g, const float* __restrict__ ln_b,
    const float* __restrict__ pe)
{
    pdl_sync();
    int b = blockIdx.x, t = threadIdx.x;
    __shared__ float sc[4];
    __shared__ float red[32];
    if (t == 0) {
        float vals[4], mx = -3.0e38f;
        #pragma unroll
        for (int l = 0; l < 4; l++) {
            float v = (g_valid[b * 4 + l] > 0.5f) ? g_s1[b * 4 + l] : -1e9f;
            vals[l] = v; mx = fmaxf(mx, v);
        }
        float s = 0.f;
        #pragma unroll
        for (int l = 0; l < 4; l++) { float e = expf(vals[l] - mx); sc[l] = e; s += e; }
        #pragma unroll
        for (int l = 0; l < 4; l++) sc[l] /= s;
    }
    __syncthreads();
    float x = sc[0] * g_hblk[(b * 4 + 0) * D_ + t] + sc[1] * g_hblk[(b * 4 + 1) * D_ + t]
            + sc[2] * g_hblk[(b * 4 + 2) * D_ + t] + sc[3] * g_hblk[(b * 4 + 3) * D_ + t]
            + pe[t];
    float mean = blockSum(x, red) * (1.f / 512.f);
    float d = x - mean;
    float var = blockSum(d * d, red) * (1.f / 512.f);
    g_bt[b * D_ + t] = d * rsqrtf(var + 1e-5f) * ln_g[t] + ln_b[t];
}

// warp-per-row H build
__global__ __launch_bounds__(256) void k_buildH(
    const float* __restrict__ emb, const float* __restrict__ pe,
    const float* __restrict__ seg_emb, const float* __restrict__ ln_g,
    const float* __restrict__ ln_b, const int* __restrict__ stc,
    const int* __restrict__ off)
{
    __shared__ float s_seg[2][D_];
    __shared__ float s_g[D_];
    __shared__ float s_b[D_];
    int b = blockIdx.x;
    int tid = threadIdx.x, lane = tid & 31, warp = tid >> 5;
    for (int i = tid; i < D_; i += 256) {
        s_seg[0][i] = seg_emb[i];
        s_seg[1][i] = seg_emb[D_ + i];
        s_g[i] = ln_g[i];
        s_b[i] = ln_b[i];
    }
    int len = stc[b];
    int pos = off[b];
    __syncthreads();
    for (int s = warp; s < len; s += 8) {
        int ip = (s < pos) ? (pos - s) : (s + 1 - pos);
        ip = ip < 0 ? 0 : (ip > S_ ? S_ : ip);
        int sg = (s >= pos) ? 1 : 0;
        const float* er = emb + ((long)b * S_ + s) * D_;
        const float* pr = pe + (long)ip * D_;
        float x[16];
        float sum = 0.f;
        #pragma unroll
        for (int i = 0; i < 4; i++) {
            int base = i * 128 + lane * 4;
            float4 e = *(const float4*)(er + base);
            float4 p = *(const float4*)(pr + base);
            float v0 = e.x + p.x + s_seg[sg][base + 0];
            float v1 = e.y + p.y + s_seg[sg][base + 1];
            float v2 = e.z + p.z + s_seg[sg][base + 2];
            float v3 = e.w + p.w + s_seg[sg][base + 3];
            x[i*4+0] = v0; x[i*4+1] = v1; x[i*4+2] = v2; x[i*4+3] = v3;
            sum += v0 + v1 + v2 + v3;
        }
        float mean = warpAll(sum) * (1.f / 512.f);
        float vs = 0.f;
        #pragma unroll
        for (int i = 0; i < 16; i++) {
            float d = x[i] - mean;
            x[i] = d;
            vs += d * d;
        }
        float inv = rsqrtf(warpAll(vs) * (1.f / 512.f) + 1e-5f);
        __half* dr = g_Hh + ((long)b * S_ + s) * D_;
        #pragma unroll
        for (int i = 0; i < 4; i++) {
            int base = i * 128 + lane * 4;
            float o0 = x[i*4+0] * inv * s_g[base + 0] + s_b[base + 0];
            float o1 = x[i*4+1] * inv * s_g[base + 1] + s_b[base + 1];
            float o2 = x[i*4+2] * inv * s_g[base + 2] + s_b[base + 2];
            float o3 = x[i*4+3] * inv * s_g[base + 3] + s_b[base + 3];
            __half2 ha = __floats2half2_rn(o0, o1);
            __half2 hb = __floats2half2_rn(o2, o3);
            *(__half2*)(dr + base)     = ha;
            *(__half2*)(dr + base + 2) = hb;
        }
    }
}

// ---------------- fused attention v4: m32n8k16 scores + m8n32k16 ctx -----------
__global__ __launch_bounds__(256) void k_attn(
    const float* __restrict__ bk, const float* __restrict__ bq,
    const int* __restrict__ stc)
{
    pdl_sync();
    int b = blockIdx.x;
    int tid = threadIdx.x, lane = tid & 31, warp = tid >> 5;   // 8 warps
    extern __shared__ __align__(16) char asm_[];
    __half* Hs   = (__half*)(asm_ + AOFF_HS);    // 32 x 520 half
    __half* uKh  = (__half*)(asm_ + AOFF_UKH);   // 8 x 520 half
    __half* uKl  = (__half*)(asm_ + AOFF_UKL);
    float* scb   = (float*)(asm_ + AOFF_SC);     // 8 x 256 (warp scratch)
    float* ps    = (float*)(asm_ + AOFF_PS);     // 32 x 8
    __half* psTh = (__half*)(asm_ + AOFF_PTH);   // 8 x 40 half
    __half* psTl = (__half*)(asm_ + AOFF_PTL);
    float* cKs   = (float*)(asm_ + AOFF_CK);
    float* pss   = (float*)(asm_ + AOFF_PSS);
    int len = stc[b];

    // stage uK -> half hi/lo (8 rows)
    {
        const float* src = g_uK + (long)b * NH_ * D_;
        #pragma unroll
        for (int i = 0; i < 16; i++) {
            int idx = tid + i * 256;
            int h = idx >> 9, k = idx & 511;
            float v = src[idx];
            __half hh = __float2half(v);
            uKh[h * AHS_ROW + k] = hh;
            uKl[h * AHS_ROW + k] = __float2half(v - __half2float(hh));
        }
    }
    // cK[h] = bk_h . q_h (q composed from comb partials + bq)
    {
        int j0 = warp * 64 + lane, j1 = j0 + 32;
        float q0 = g_partC[(long)b * 2048 + j0] + g_partC[PC1_OFF + (long)b * 2048 + j0] + bq[j0];
        float q1 = g_partC[(long)b * 2048 + j1] + g_partC[PC1_OFF + (long)b * 2048 + j1] + bq[j1];
        float v = bk[j0] * q0 + bk[j1] * q1;
        v = warpSum(v);
        if (lane == 0) { cKs[warp] = v; pss[warp] = 0.f; }
    }
    // persistent ctx accumulators: warp owns n-cols [warp*64, warp*64+64)
    nvcuda::wmma::fragment<nvcuda::wmma::accumulator, 8, 32, 16, float> cacc[2];
    #pragma unroll
    for (int j = 0; j < 2; j++) nvcuda::wmma::fill_fragment(cacc[j], 0.0f);
    __syncthreads();

    int nch = (len + CH - 1) / CH;
    for (int c = 0; c < nch; c++) {
        int s0 = c * CH;
        // stage H chunk as raw half rows (zero past len)
        for (int r = warp; r < CH; r += 8) {
            int s = s0 + r;
            uint4* dst = (uint4*)(Hs + r * AHS_ROW);
            if (s < len) {
                const uint4* src = (const uint4*)(g_Hh + ((long)b * S_ + s) * D_);
                dst[lane] = src[lane];
                dst[lane + 32] = src[lane + 32];
            } else {
                uint4 z; z.x = 0; z.y = 0; z.z = 0; z.w = 0;
                dst[lane] = z;
                dst[lane + 32] = z;
            }
        }
        __syncthreads();
        // scores via WMMA m32n8k16: (32 x 512) @ (512 x 8), k split across warps
        {
            nvcuda::wmma::fragment<nvcuda::wmma::accumulator, 32, 8, 16, float> sacc;
            nvcuda::wmma::fill_fragment(sacc, 0.0f);
            #pragma unroll
            for (int kt = 0; kt < 4; kt++) {
                int k0 = (warp * 4 + kt) * 16;
                nvcuda::wmma::fragment<nvcuda::wmma::matrix_a, 32, 8, 16,
                                       __half, nvcuda::wmma::row_major> af;
                nvcuda::wmma::fragment<nvcuda::wmma::matrix_b, 32, 8, 16,
                                       __half, nvcuda::wmma::col_major> bfh, bfl;
                nvcuda::wmma::load_matrix_sync(af, Hs + k0, AHS_ROW);
                nvcuda::wmma::load_matrix_sync(bfh, uKh + k0, AHS_ROW);
                nvcuda::wmma::load_matrix_sync(bfl, uKl + k0, AHS_ROW);
                nvcuda::wmma::mma_sync(sacc, af, bfh, sacc);
                nvcuda::wmma::mma_sync(sacc, af, bfl, sacc);
            }
            nvcuda::wmma::store_matrix_sync(scb + warp * 256, sacc, 8,
                                            nvcuda::wmma::mem_row_major);
        }
        __syncthreads();
        // combine warp partials + sigmoid -> ps and psT hi/lo
        {
            int r = tid >> 3, h = tid & 7;
            float v = 0.f;
            #pragma unroll
            for (int w = 0; w < 8; w++) v += scb[w * 256 + r * 8 + h];
            int s = s0 + r;
            float p = (s < len) ? sigm(0.125f * (v + cKs[h])) : 0.f;
            ps[r * NH_ + h] = p;
            __half ph = __float2half(p);
            psTh[h * APT_ROW + r] = ph;
            psTl[h * APT_ROW + r] = __float2half(p - __half2float(ph));
        }
        __syncthreads();
        // ctx via WMMA m8n32k16: P^T(8x32 hi/lo) @ Hs(32x512)
        #pragma unroll
        for (int kt = 0; kt < 2; kt++) {
            nvcuda::wmma::fragment<nvcuda::wmma::matrix_a, 8, 32, 16,
                                   __half, nvcuda::wmma::row_major> pah, pal;
            nvcuda::wmma::load_matrix_sync(pah, psTh + kt * 16, APT_ROW);
            nvcuda::wmma::load_matrix_sync(pal, psTl + kt * 16, APT_ROW);
            #pragma unroll
            for (int j = 0; j < 2; j++) {
                nvcuda::wmma::fragment<nvcuda::wmma::matrix_b, 8, 32, 16,
                                       __half, nvcuda::wmma::row_major> hb;
                nvcuda::wmma::load_matrix_sync(hb, Hs + kt * 16 * AHS_ROW + warp * 64 + j * 32,
                                               AHS_ROW);
                nvcuda::wmma::mma_sync(cacc[j], pah, hb, cacc[j]);
                nvcuda::wmma::mma_sync(cacc[j], pal, hb, cacc[j]);
            }
        }
        // psum
        {
            float v = ps[lane * NH_ + warp];
            v = warpSum(v);
            if (lane == 0) pss[warp] += v;
        }
        __syncthreads();
    }
    // drain ctx accumulators: warp-local through its scb scratch (8x32 each)
    #pragma unroll
    for (int j = 0; j < 2; j++) {
        nvcuda::wmma::store_matrix_sync(scb + warp * 256, cacc[j], 32,
                                        nvcuda::wmma::mem_row_major);
        __syncwarp();
        int h = lane >> 2;
        int cb = (lane & 3) * 8;
        float4 v0;
        v0.x = scb[warp * 256 + h * 32 + cb + 0];
        v0.y = scb[warp * 256 + h * 32 + cb + 1];
        v0.z = scb[warp * 256 + h * 32 + cb + 2];
        v0.w = scb[warp * 256 + h * 32 + cb + 3];
        float4 v1;
        v1.x = scb[warp * 256 + h * 32 + cb + 4];
        v1.y = scb[warp * 256 + h * 32 + cb + 5];
        v1.z = scb[warp * 256 + h * 32 + cb + 6];
        v1.w = scb[warp * 256 + h * 32 + cb + 7];
        long o = ((long)b * NH_ + h) * D_ + warp * 64 + j * 32 + cb;
        *(float4*)&g_ctx[o] = v0;
        *(float4*)&g_ctx[o + 4] = v1;
        __syncwarp();
    }
    if (tid < NH_) g_psum[b * NH_ + tid] = pss[tid];
}

// ---------------- small per-iter kernels --------------------------------------
__global__ __launch_bounds__(512) void k_ln_mt(
    const float* __restrict__ bv, const float* __restrict__ lng_g,
    const float* __restrict__ lng_b)
{
    pdl_sync();
    int b = blockIdx.x, t = threadIdx.x;
    __shared__ float red[32];
    long o = (long)b * 512 + t;
    float x = g_partM[o] + g_partM[PM_OFF + o] + g_partM[2 * PM_OFF + o]
            + g_partM[3 * PM_OFF + o] + g_psum[b * NH_ + (t >> 6)] * bv[t];
    float mean = blockSum(x, red) * (1.f / 512.f);
    float d = x - mean;
    float var = blockSum(d * d, red) * (1.f / 512.f);
    g_mt[b * D_ + t] = d * rsqrtf(var + 1e-5f) * lng_g[t] + lng_b[t];
}

__global__ __launch_bounds__(512) void k_gru(
    const float* __restrict__ b_ih, const float* __restrict__ b_hh,
    float* __restrict__ out, int last)
{
    int b = blockIdx.x, t = threadIdx.x;
    const float* G0 = g_partG + (long)b * 1536;
    const float* G1 = g_partG + PG1_OFF + (long)b * 1536;
    const float* C0 = g_partC + (long)b * 2048 + 512;
    const float* C1 = g_partC + PC1_OFF + (long)b * 2048 + 512;
    float ir = G0[t]        + G1[t]        + b_ih[t];
    float iz = G0[t + 512]  + G1[t + 512]  + b_ih[t + 512];
    float in = G0[t + 1024] + G1[t + 1024] + b_ih[t + 1024];
    float hr = C0[t]        + C1[t]        + b_hh[t];
    float hz = C0[t + 512]  + C1[t + 512]  + b_hh[t + 512];
    float hn = C0[t + 1024] + C1[t + 1024] + b_hh[t + 1024];
    float r = sigm(ir + hr);
    float z = sigm(iz + hz);
    float n = tanhf(in + r * hn);
    float old = g_bt[b * D_ + t];
    float nv = (1.f - z) * n + z * old;
    g_bt[b * D_ + t] = nv;
    if (last) out[b * 512 + t] = nv;
}

// ---------------- launch --------------------------------------------------------
extern "C" void kernel_launch(void* const* d_in, const int* in_sizes, int n_in,
                              void* d_out, int out_size)
{
    const float* emb   = (const float*)d_in[0];
    const int*   stc   = (const int*)  d_in[1];
    const int*   off   = (const int*)  d_in[2];
    const int*   sep   = (const int*)  d_in[3];
    const float* W1    = (const float*)d_in[4];
    const float* W2    = (const float*)d_in[5];
    const float* ln_g  = (const float*)d_in[6];
    const float* ln_b  = (const float*)d_in[7];
    const float* lng_g = (const float*)d_in[8];
    const float* lng_b = (const float*)d_in[9];
    const float* Wq    = (const float*)d_in[10];
    const float* bq    = (const float*)d_in[11];
    const float* Wk    = (const float*)d_in[12];
    const float* bk    = (const float*)d_in[13];
    const float* Wv    = (const float*)d_in[14];
    const float* bv    = (const float*)d_in[15];
    const float* W_ih  = (const float*)d_in[16];
    const float* W_hh  = (const float*)d_in[17];
    const float* b_ih  = (const float*)d_in[18];
    const float* b_hh  = (const float*)d_in[19];
    const float* seg   = (const float*)d_in[20];
    const float* pe    = (const float*)d_in[21];
    float* out = (float*)d_out;

    cudaFuncSetAttribute(k_attn, cudaFuncAttributeMaxDynamicSharedMemorySize, ATTN_SMEM_V4);
    cudaFuncSetAttribute(k_tc_w1,   cudaFuncAttributeMaxDynamicSharedMemorySize, SMEM_TCB128);
    cudaFuncSetAttribute(k_tc_q,    cudaFuncAttributeMaxDynamicSharedMemorySize, SMEM_TCB64);
    cudaFuncSetAttribute(k_tc_gh,   cudaFuncAttributeMaxDynamicSharedMemorySize, SMEM_TCB128);
    cudaFuncSetAttribute(k_tc_uk,   cudaFuncAttributeMaxDynamicSharedMemorySize, SMEM_TCB128);
    cudaFuncSetAttribute(k_tc_gi,   cudaFuncAttributeMaxDynamicSharedMemorySize, SMEM_TCB128);
    cudaFuncSetAttribute(k_tc_mraw, cudaFuncAttributeMaxDynamicSharedMemorySize, SMEM_TCB64);

    cudaStream_t sB;
    cudaStreamCreateWithFlags(&sB, cudaStreamNonBlocking);
    cudaEvent_t evF, evH, evG;
    cudaEventCreateWithFlags(&evF, cudaEventDisableTiming);
    cudaEventCreateWithFlags(&evH, cudaEventDisableTiming);
    cudaEventCreateWithFlags(&evG, cudaEventDisableTiming);

    cudaLaunchAttribute pdlAttr[1];
    pdlAttr[0].id = cudaLaunchAttributeProgrammaticStreamSerialization;
    pdlAttr[0].val.programmaticStreamSerializationAllowed = 1;
    auto mkcfg = [&](dim3 g, dim3 b, size_t smem) {
        cudaLaunchConfig_t c;
        c.gridDim = g; c.blockDim = b; c.dynamicSmemBytes = smem;
        c.stream = 0; c.attrs = pdlAttr; c.numAttrs = 1;
        return c;
    };

    // ---- preamble: side stream does non-critical weight prep + buildH ----
    cudaEventRecord(evF, 0);
    cudaStreamWaitEvent(sB, evF, 0);
    k_prep<<<dim3(16, 48, 5), 256, 0, sB>>>(Wk, W_ih, W_hh, Wq, Wv, W1, 0);
    k_buildH<<<B_, 256, 0, sB>>>(emb, pe, seg, ln_g, ln_b, stc, off);
    cudaEventRecord(evH, sB);

    // critical preamble chain: W1 split -> hblk -> W1 GEMM -> a -> s1 -> b0
    k_prep<<<dim3(16, 16, 1), 256>>>(Wk, W_ih, W_hh, Wq, Wv, W1, 5);
    {
        cudaLaunchConfig_t c = mkcfg(dim3(B_, 1, 1), dim3(512, 1, 1), 0);
        cudaLaunchKernelEx(&c, k_build_hblk, emb, stc, off, sep);
    }
    {
        cudaLaunchConfig_t c = mkcfg(dim3(4, 32, 2), dim3(256, 1, 1), SMEM_TCB128);
        cudaLaunchKernelEx(&c, k_tc_w1);
    }
    {
        cudaLaunchConfig_t c = mkcfg(dim3(2048, 1, 1), dim3(256, 1, 1), 0);
        cudaLaunchKernelEx(&c, k_a, W2);
    }
    {
        cudaLaunchConfig_t c = mkcfg(dim3(L_, 1, 1), dim3(512, 1, 1), 0);
        cudaLaunchKernelEx(&c, k_s1);
    }
    {
        cudaLaunchConfig_t c = mkcfg(dim3(B_, 1, 1), dim3(512, 1, 1), 0);
        cudaLaunchKernelEx(&c, k_b0, ln_g, ln_b, pe);
    }
    // join side stream: weights + H ready before first iteration GEMMs
    cudaStreamWaitEvent(0, evH, 0);

    // ---- 3 GRU iterations ----
    for (int it = 0; it < 3; it++) {
        cudaEventRecord(evF, 0);
        cudaStreamWaitEvent(sB, evF, 0);
        k_tc_gh<<<dim3(12, 8, 2), 256, SMEM_TCB128, sB>>>();
        cudaEventRecord(evG, sB);

        {
            cudaLaunchConfig_t c = mkcfg(dim3(8, 8, 2), dim3(256, 1, 1), SMEM_TCB64);
            cudaLaunchKernelEx(&c, k_tc_q);
        }
        {
            cudaLaunchConfig_t c = mkcfg(dim3(4, 8, 8), dim3(256, 1, 1), SMEM_TCB128);
            cudaLaunchKernelEx(&c, k_tc_uk, bq);
        }
        {
            cudaLaunchConfig_t c = mkcfg(dim3(B_, 1, 1), dim3(256, 1, 1), ATTN_SMEM_V4);
            cudaLaunchKernelEx(&c, k_attn, bk, bq, stc);
        }
        {
            cudaLaunchConfig_t c = mkcfg(dim3(1, 8, 32), dim3(256, 1, 1), SMEM_TCB64);
            cudaLaunchKernelEx(&c, k_tc_mraw);
        }
        {
            cudaLaunchConfig_t c = mkcfg(dim3(B_, 1, 1), dim3(512, 1, 1), 0);
            cudaLaunchKernelEx(&c, k_ln_mt, bv, lng_g, lng_b);
        }
        {
            cudaLaunchConfig_t c = mkcfg(dim3(12, 8, 2), dim3(256, 1, 1), SMEM_TCB128);
            cudaLaunchKernelEx(&c, k_tc_gi);
        }
        cudaStreamWaitEvent(0, evG, 0);
        k_gru<<<B_, 512>>>(b_ih, b_hh, out, it == 2 ? 1 : 0);
    }
    (void)in_sizes; (void)n_in; (void)out_size;
}